// round 13
// baseline (speedup 1.0000x reference)
#include <cuda_runtime.h>
#include <cuda_bf16.h>
#include <cstdint>
#include <math.h>

// NT-Xent loss, N=4096, D=256.
// loss = mean_i( log(sum_{j!=i} e^{2 zn_i.zn_j}) - 2 zn_i.zn_{i^4096} )
// R13: FP8 (e4m3) mma.sync m16n8k32 — halves MMA instruction count and ldsm
//      fragment traffic vs bf16 m16n8k16 (R11 was pinned at the HMMA issue floor).

#define NROWS 8192
#define NHALF 4096
#define DDIM  256
#define BM 128
#define NTILE 64
#define NCTA 148
#define NTHREADS 512
#define TILE_BYTES (BM * DDIM)            // 32768 (128 x 256 fp8)
#define RED_BYTES (8 * BM * 4)

__device__ __align__(16) uint8_t g_zb[NROWS * DDIM];   // e4m3
__device__ float g_rowsum[NROWS];
__device__ float g_pair[NROWS];
__device__ unsigned g_cnt1;
__device__ unsigned g_cnt2;

// ---------------------------------------------------------------- helpers
__device__ __forceinline__ uint32_t smem_u32(const void* p) {
    uint32_t a;
    asm("{ .reg .u64 t; cvta.to.shared.u64 t, %1; cvt.u32.u64 %0, t; }" : "=r"(a) : "l"(p));
    return a;
}
__device__ __forceinline__ void ldsm_x4(uint32_t addr, uint32_t* r) {
    asm volatile("ldmatrix.sync.aligned.m8n8.x4.shared.b16 {%0,%1,%2,%3}, [%4];"
        : "=r"(r[0]), "=r"(r[1]), "=r"(r[2]), "=r"(r[3]) : "r"(addr));
}
__device__ __forceinline__ void mma_fp8(float* c, const uint32_t* a, const uint32_t* b) {
    asm volatile("mma.sync.aligned.m16n8k32.row.col.f32.e4m3.e4m3.f32 "
        "{%0,%1,%2,%3}, {%4,%5,%6,%7}, {%8,%9}, {%0,%1,%2,%3};"
        : "+f"(c[0]), "+f"(c[1]), "+f"(c[2]), "+f"(c[3])
        : "r"(a[0]), "r"(a[1]), "r"(a[2]), "r"(a[3]), "r"(b[0]), "r"(b[1]));
}
__device__ __forceinline__ void cp_async16(uint32_t dst, const void* src) {
    asm volatile("cp.async.cg.shared.global [%0], [%1], 16;" :: "r"(dst), "l"(src));
}
#define CP_COMMIT() asm volatile("cp.async.commit_group;" ::: "memory")
#define CP_WAIT0()  asm volatile("cp.async.wait_group 0;" ::: "memory")

// e4m3x2 pack: low byte = lo, high byte = hi
__device__ __forceinline__ uint16_t f2e4m3x2(float hi, float lo) {
    uint16_t r;
    asm("cvt.rn.satfinite.e4m3x2.f32 %0, %1, %2;" : "=h"(r) : "f"(hi), "f"(lo));
    return r;
}

// fp8 tile: 128 rows x 256 B; 16 chunks of 16 B per row; swizzle c^(r&7)
__device__ __forceinline__ uint32_t tile_addr(uint32_t base, int row, int chunk) {
    return base + (uint32_t)row * 256u + (uint32_t)((chunk ^ (row & 7)) << 4);
}
__device__ __forceinline__ int rowof(int p) {
    return (p & 1) ? (NTILE - 1 - (p >> 1)) : (p >> 1);
}
__device__ __forceinline__ void tile_load(uint32_t ubase, int row0, int tid) {
    #pragma unroll
    for (int it = 0; it < 4; it++) {
        int idx = tid + it * NTHREADS;      // 2048 16B chunks
        int r = idx >> 4, c = idx & 15;
        cp_async16(tile_addr(ubase, r, c), g_zb + (size_t)(row0 + r) * DDIM + c * 16);
    }
}

// ---------------------------------------------------------- fused persistent kernel
__global__ __launch_bounds__(NTHREADS, 1) void k_fused(const float* __restrict__ z1,
                                                       const float* __restrict__ z2,
                                                       float* __restrict__ out) {
    extern __shared__ __align__(16) char dyn[];
    const int tid = threadIdx.x;
    const int wid = tid >> 5;
    const int lane = tid & 31;
    const int wm = wid & 3;
    const int wn = wid >> 2;
    const int cta = blockIdx.x;

    // ---------------- phase 1: normalize -> e4m3 (warp per row) -------------------
    #pragma unroll
    for (int it = 0; it < 4; it++) {
        const int grp = cta + it * NCTA;
        if (grp < NROWS / 16) {
            const int row = grp * 16 + wid;
            const float* src = (row < NHALF) ? (z1 + (size_t)row * DDIM)
                                             : (z2 + (size_t)(row - NHALF) * DDIM);
            // lane holds 8 contiguous elements [lane*8 .. lane*8+8)
            float4 v0 = ((const float4*)src)[lane * 2];
            float4 v1 = ((const float4*)src)[lane * 2 + 1];
            float ss = v0.x * v0.x + v0.y * v0.y + v0.z * v0.z + v0.w * v0.w
                     + v1.x * v1.x + v1.y * v1.y + v1.z * v1.z + v1.w * v1.w;
            #pragma unroll
            for (int o = 16; o; o >>= 1) ss += __shfl_xor_sync(0xFFFFFFFFu, ss, o);
            const float rn = 1.0f / fmaxf(sqrtf(ss), 1e-8f);
            uint16_t p0 = f2e4m3x2(v0.y * rn, v0.x * rn);
            uint16_t p1 = f2e4m3x2(v0.w * rn, v0.z * rn);
            uint16_t p2 = f2e4m3x2(v1.y * rn, v1.x * rn);
            uint16_t p3 = f2e4m3x2(v1.w * rn, v1.z * rn);
            uint2 packed;
            packed.x = (uint32_t)p0 | ((uint32_t)p1 << 16);
            packed.y = (uint32_t)p2 | ((uint32_t)p3 << 16);
            ((uint2*)(g_zb + (size_t)row * DDIM))[lane] = packed;
            if (lane == 0) g_rowsum[row] = 0.0f;
        }
    }

    // ---------------- grid barrier 1 ----------------------------------------------
    if (tid == 0) {
        __threadfence();
        atomicAdd(&g_cnt1, 1u);
        while (*(volatile unsigned*)&g_cnt1 < NCTA) { }
        __threadfence();
    }
    __syncthreads();

    // ---------------- phase 2: symmetric FP8 MMA GEMM + exp + sums + pair ----------
    uint32_t d32 = smem_u32(dyn);
    char* base = dyn + ((1024u - (d32 & 1023u)) & 1023u);
    const uint32_t uA  = smem_u32(base);
    const uint32_t uB0 = uA + TILE_BYTES;
    const uint32_t uB1 = uA + 2 * TILE_BYTES;
    float* red_row = (float*)(base + 3 * TILE_BYTES);
    float* red_col = red_row + 4 * BM;

    // hoisted ldsm addresses: chunk = (2ks+hl)^(r&7) with disjoint bits:
    // addr = [base + r*256 + ((hl^(r&1))<<4)] + ((ks<<5) ^ ((r&6)<<4))
    const int hl = lane >> 4;
    uint32_t PA[2], SA[2];
    #pragma unroll
    for (int mf = 0; mf < 2; mf++) {
        int r = wm * 32 + mf * 16 + (lane & 15);
        PA[mf] = uA + (uint32_t)r * 256u + (uint32_t)((hl ^ (r & 1)) << 4);
        SA[mf] = (uint32_t)((r & 6) << 4);
    }
    uint32_t PBo[2], SB[2];
    #pragma unroll
    for (int ng = 0; ng < 2; ng++) {
        int rn = wn * 32 + ng * 16 + (lane & 15);
        PBo[ng] = (uint32_t)rn * 256u + (uint32_t)((hl ^ (rn & 1)) << 4);
        SB[ng] = (uint32_t)((rn & 6) << 4);
    }

    const int count = 14 + (cta < 8 ? 1 : 0);
    int rem = cta * 14 + (cta < 8 ? cta : 8);
    int p = 0;
    for (;;) {
        int L = NTILE - rowof(p);
        if (rem < L) break;
        rem -= L;
        p++;
    }
    int off = rem;

    int ti = rowof(p);
    tile_load(uA, ti * BM, tid);
    tile_load(uB0, (ti + off) * BM, tid);
    CP_COMMIT();
    int cur_ti = ti;

    for (int k = 0; k < count; k++) {
        ti = rowof(p);
        const int tj = ti + off;
        if (ti != cur_ti) {
            tile_load(uA, ti * BM, tid);
            CP_COMMIT();
            cur_ti = ti;
        }
        CP_WAIT0();
        __syncthreads();

        if (k + 1 < count) {
            int p2 = p, o2 = off + 1;
            if (o2 >= NTILE - rowof(p2)) { o2 = 0; p2++; }
            tile_load((k & 1) ? uB0 : uB1, (rowof(p2) + o2) * BM, tid);
            CP_COMMIT();
        }

        const uint32_t uBc = (k & 1) ? uB1 : uB0;
        const int i0 = ti * BM, j0 = tj * BM;
        const bool diag = (ti == tj);
        const bool pairt = (tj == ti + NHALF / BM);

        float acc[2][4][4];
        #pragma unroll
        for (int mf = 0; mf < 2; mf++)
            #pragma unroll
            for (int nf = 0; nf < 4; nf++)
                #pragma unroll
                for (int c = 0; c < 4; c++) acc[mf][nf][c] = 0.0f;

        // ---- k-loop (8 steps of K=32), register double-buffered fragments ----
        uint32_t af[2][2][4], bf[2][4][2];
        {
            #pragma unroll
            for (int mf = 0; mf < 2; mf++)
                ldsm_x4(PA[mf] + (0u ^ SA[mf]), af[0][mf]);
            #pragma unroll
            for (int ng = 0; ng < 2; ng++) {
                uint32_t q[4];
                ldsm_x4(uBc + PBo[ng] + (0u ^ SB[ng]), q);
                bf[0][ng * 2 + 0][0] = q[0]; bf[0][ng * 2 + 0][1] = q[2];
                bf[0][ng * 2 + 1][0] = q[1]; bf[0][ng * 2 + 1][1] = q[3];
            }
        }
        #pragma unroll
        for (int ks = 0; ks < 8; ks++) {
            const int cur = ks & 1, nxt = cur ^ 1;
            if (ks < 7) {
                const uint32_t kbit = (uint32_t)((ks + 1) << 5);
                #pragma unroll
                for (int mf = 0; mf < 2; mf++)
                    ldsm_x4(PA[mf] + (kbit ^ SA[mf]), af[nxt][mf]);
                #pragma unroll
                for (int ng = 0; ng < 2; ng++) {
                    uint32_t q[4];
                    ldsm_x4(uBc + PBo[ng] + (kbit ^ SB[ng]), q);
                    bf[nxt][ng * 2 + 0][0] = q[0]; bf[nxt][ng * 2 + 0][1] = q[2];
                    bf[nxt][ng * 2 + 1][0] = q[1]; bf[nxt][ng * 2 + 1][1] = q[3];
                }
            }
            #pragma unroll
            for (int mf = 0; mf < 2; mf++)
                #pragma unroll
                for (int nf = 0; nf < 4; nf++)
                    mma_fp8(acc[mf][nf], af[cur][mf], bf[cur][nf]);
        }

        // ---- epilogue: pair capture, exp, diagonal mask, row+col sums ----
        const int rloc = wm * 32 + (lane >> 2);
        const int cloc = wn * 32 + (lane & 3) * 2;
        float cs[8];
        #pragma unroll
        for (int x = 0; x < 8; x++) cs[x] = 0.0f;

        #pragma unroll
        for (int mf = 0; mf < 2; mf++) {
            const int rlo = i0 + rloc + mf * 16;
            const int rhi = rlo + 8;
            float slo = 0.0f, shi = 0.0f;
            #pragma unroll
            for (int nf = 0; nf < 4; nf++) {
                const int col = j0 + cloc + nf * 8;
                if (pairt) {
                    if ((rlo ^ NHALF) == col) {
                        float v = 2.0f * acc[mf][nf][0];
                        g_pair[rlo] = v; g_pair[col] = v;
                    }
                    if ((rlo ^ NHALF) == col + 1) {
                        float v = 2.0f * acc[mf][nf][1];
                        g_pair[rlo] = v; g_pair[col + 1] = v;
                    }
                    if ((rhi ^ NHALF) == col) {
                        float v = 2.0f * acc[mf][nf][2];
                        g_pair[rhi] = v; g_pair[col] = v;
                    }
                    if ((rhi ^ NHALF) == col + 1) {
                        float v = 2.0f * acc[mf][nf][3];
                        g_pair[rhi] = v; g_pair[col + 1] = v;
                    }
                }
                float e0 = __expf(2.0f * acc[mf][nf][0]);
                float e1 = __expf(2.0f * acc[mf][nf][1]);
                float e2 = __expf(2.0f * acc[mf][nf][2]);
                float e3 = __expf(2.0f * acc[mf][nf][3]);
                e0 = (rlo == col)     ? 0.0f : e0;
                e1 = (rlo == col + 1) ? 0.0f : e1;
                e2 = (rhi == col)     ? 0.0f : e2;
                e3 = (rhi == col + 1) ? 0.0f : e3;
                slo += e0 + e1;
                shi += e2 + e3;
                cs[nf * 2]     += e0 + e2;
                cs[nf * 2 + 1] += e1 + e3;
            }
            slo += __shfl_xor_sync(0xFFFFFFFFu, slo, 1);
            slo += __shfl_xor_sync(0xFFFFFFFFu, slo, 2);
            shi += __shfl_xor_sync(0xFFFFFFFFu, shi, 1);
            shi += __shfl_xor_sync(0xFFFFFFFFu, shi, 2);
            if ((lane & 3) == 0) {
                const int lrow = wm * 32 + mf * 16 + (lane >> 2);
                red_row[wn * BM + lrow] = slo;
                red_row[wn * BM + lrow + 8] = shi;
            }
        }
        if (!diag) {
            #pragma unroll
            for (int x = 0; x < 8; x++) {
                cs[x] += __shfl_xor_sync(0xFFFFFFFFu, cs[x], 4);
                cs[x] += __shfl_xor_sync(0xFFFFFFFFu, cs[x], 8);
                cs[x] += __shfl_xor_sync(0xFFFFFFFFu, cs[x], 16);
            }
            if (lane < 4) {
                #pragma unroll
                for (int nf = 0; nf < 4; nf++) {
                    const int c = wn * 32 + nf * 8 + lane * 2;
                    red_col[wm * BM + c]     = cs[nf * 2];
                    red_col[wm * BM + c + 1] = cs[nf * 2 + 1];
                }
            }
        }
        __syncthreads();
        if (tid < BM) {
            float s = red_row[tid] + red_row[BM + tid]
                    + red_row[2 * BM + tid] + red_row[3 * BM + tid];
            atomicAdd(&g_rowsum[i0 + tid], s);
        } else if (tid < 2 * BM && !diag) {
            const int c = tid - BM;
            float s = red_col[c] + red_col[BM + c]
                    + red_col[2 * BM + c] + red_col[3 * BM + c];
            atomicAdd(&g_rowsum[j0 + c], s);
        }

        off++;
        if (off >= NTILE - ti) { off = 0; p++; }
    }

    // ---------------- grid barrier 2 + CTA0 finish ---------------------------------
    if (tid == 0) {
        __threadfence();
        atomicAdd(&g_cnt2, 1u);
    }
    if (cta == 0) {
        if (tid == 0) {
            while (*(volatile unsigned*)&g_cnt2 < NCTA) { }
            __threadfence();
        }
        __syncthreads();
        __shared__ float sh[NTHREADS];
        float s = 0.0f;
        #pragma unroll
        for (int u = 0; u < NROWS / NTHREADS; u++) {
            const int r = tid + u * NTHREADS;
            s += logf(g_rowsum[r]) - g_pair[r];
        }
        sh[tid] = s;
        __syncthreads();
        for (int o2 = NTHREADS / 2; o2; o2 >>= 1) {
            if (tid < o2) sh[tid] += sh[tid + o2];
            __syncthreads();
        }
        if (tid == 0) {
            out[0] = sh[0] * (1.0f / (float)NROWS);
            g_cnt1 = 0;
            g_cnt2 = 0;
        }
    }
}

// ---------------------------------------------------------------- launch
extern "C" void kernel_launch(void* const* d_in, const int* in_sizes, int n_in,
                              void* d_out, int out_size) {
    const float* z1 = (const float*)d_in[0];
    const float* z2 = (const float*)d_in[1];
    float* out = (float*)d_out;

    static int smem_set = 0;
    if (!smem_set) {
        cudaFuncSetAttribute(k_fused, cudaFuncAttributeMaxDynamicSharedMemorySize,
                             3 * TILE_BYTES + RED_BYTES + 1024);
        smem_set = 1;
    }

    k_fused<<<NCTA, NTHREADS, 3 * TILE_BYTES + RED_BYTES + 1024>>>(z1, z2, out);
}

// round 14
// speedup vs baseline: 1.0439x; 1.0439x over previous
#include <cuda_runtime.h>
#include <cuda_bf16.h>
#include <cstdint>
#include <math.h>

// NT-Xent loss, N=4096, D=256.
// loss = mean_i( log(sum_{j!=i} e^{2 zn_i.zn_j}) - 2 zn_i.zn_{i^4096} )
// R14: fp8 symmetric GEMM with 128x64 tiles, 256 threads/CTA, 2 CTAs/SM
//      (296 persistent CTAs) so one CTA's epilogue overlaps the other's MMAs.

#define NROWS 8192
#define NHALF 4096
#define DDIM  256
#define BM 128
#define BN 64
#define NTILE 64                   // 128-row blocks
#define NCOLT 128                  // 64-col blocks
#define NCTA 296
#define NTHREADS 256
#define A_BYTES (BM * DDIM)        // 32768
#define B_BYTES (BN * DDIM)        // 16384
#define RED_BYTES 2048             // red_row[2][128] + red_col[4][64]
#define DYN_BYTES (A_BYTES + 2 * B_BYTES + RED_BYTES + 1024)

__device__ __align__(16) uint8_t g_zb[NROWS * DDIM];   // e4m3
__device__ float g_rowsum[NROWS];
__device__ float g_pair[NROWS];
__device__ unsigned g_cnt1;
__device__ unsigned g_cnt2;

// ---------------------------------------------------------------- helpers
__device__ __forceinline__ uint32_t smem_u32(const void* p) {
    uint32_t a;
    asm("{ .reg .u64 t; cvta.to.shared.u64 t, %1; cvt.u32.u64 %0, t; }" : "=r"(a) : "l"(p));
    return a;
}
__device__ __forceinline__ void ldsm_x4(uint32_t addr, uint32_t* r) {
    asm volatile("ldmatrix.sync.aligned.m8n8.x4.shared.b16 {%0,%1,%2,%3}, [%4];"
        : "=r"(r[0]), "=r"(r[1]), "=r"(r[2]), "=r"(r[3]) : "r"(addr));
}
__device__ __forceinline__ void mma_fp8(float* c, const uint32_t* a, const uint32_t* b) {
    asm volatile("mma.sync.aligned.m16n8k32.row.col.f32.e4m3.e4m3.f32 "
        "{%0,%1,%2,%3}, {%4,%5,%6,%7}, {%8,%9}, {%0,%1,%2,%3};"
        : "+f"(c[0]), "+f"(c[1]), "+f"(c[2]), "+f"(c[3])
        : "r"(a[0]), "r"(a[1]), "r"(a[2]), "r"(a[3]), "r"(b[0]), "r"(b[1]));
}
__device__ __forceinline__ void cp_async16(uint32_t dst, const void* src) {
    asm volatile("cp.async.cg.shared.global [%0], [%1], 16;" :: "r"(dst), "l"(src));
}
#define CP_COMMIT() asm volatile("cp.async.commit_group;" ::: "memory")
#define CP_WAIT0()  asm volatile("cp.async.wait_group 0;" ::: "memory")

__device__ __forceinline__ uint16_t f2e4m3x2(float hi, float lo) {
    uint16_t r;
    asm("cvt.rn.satfinite.e4m3x2.f32 %0, %1, %2;" : "=h"(r) : "f"(hi), "f"(lo));
    return r;
}
// fp8 tile rows: 256B, 16 chunks of 16B, swizzle c^(r&7)
__device__ __forceinline__ uint32_t tile_addr(uint32_t base, int row, int chunk) {
    return base + (uint32_t)row * 256u + (uint32_t)((chunk ^ (row & 7)) << 4);
}
__device__ __forceinline__ int rowof(int p) {
    return (p & 1) ? (NTILE - 1 - (p >> 1)) : (p >> 1);
}
__device__ __forceinline__ void load_A(uint32_t ubase, int row0, int tid) {
    #pragma unroll
    for (int it = 0; it < 8; it++) {                 // 2048 chunks
        int idx = tid + it * NTHREADS;
        int r = idx >> 4, c = idx & 15;
        cp_async16(tile_addr(ubase, r, c), g_zb + (size_t)(row0 + r) * DDIM + c * 16);
    }
}
__device__ __forceinline__ void load_B(uint32_t ubase, int row0, int tid) {
    #pragma unroll
    for (int it = 0; it < 4; it++) {                 // 1024 chunks
        int idx = tid + it * NTHREADS;
        int r = idx >> 4, c = idx & 15;
        cp_async16(tile_addr(ubase, r, c), g_zb + (size_t)(row0 + r) * DDIM + c * 16);
    }
}

// ---------------------------------------------------------- fused persistent kernel
__global__ __launch_bounds__(NTHREADS, 2) void k_fused(const float* __restrict__ z1,
                                                       const float* __restrict__ z2,
                                                       float* __restrict__ out) {
    extern __shared__ __align__(16) char dyn[];
    const int tid = threadIdx.x;
    const int wid = tid >> 5;
    const int lane = tid & 31;
    const int wm = wid & 3;            // 4 row groups of 32
    const int wn = wid >> 2;           // 2 col groups of 32
    const int cta = blockIdx.x;

    // ---------------- phase 1: normalize -> e4m3 (warp per row) -------------------
    #pragma unroll
    for (int it = 0; it < 4; it++) {
        const int grp = cta + it * NCTA;            // 8-row group
        if (grp < NROWS / 8) {
            const int row = grp * 8 + wid;
            const float* src = (row < NHALF) ? (z1 + (size_t)row * DDIM)
                                             : (z2 + (size_t)(row - NHALF) * DDIM);
            float4 v0 = ((const float4*)src)[lane * 2];
            float4 v1 = ((const float4*)src)[lane * 2 + 1];
            float ss = v0.x * v0.x + v0.y * v0.y + v0.z * v0.z + v0.w * v0.w
                     + v1.x * v1.x + v1.y * v1.y + v1.z * v1.z + v1.w * v1.w;
            #pragma unroll
            for (int o = 16; o; o >>= 1) ss += __shfl_xor_sync(0xFFFFFFFFu, ss, o);
            const float rn = 1.0f / fmaxf(sqrtf(ss), 1e-8f);
            uint16_t p0 = f2e4m3x2(v0.y * rn, v0.x * rn);
            uint16_t p1 = f2e4m3x2(v0.w * rn, v0.z * rn);
            uint16_t p2 = f2e4m3x2(v1.y * rn, v1.x * rn);
            uint16_t p3 = f2e4m3x2(v1.w * rn, v1.z * rn);
            uint2 packed;
            packed.x = (uint32_t)p0 | ((uint32_t)p1 << 16);
            packed.y = (uint32_t)p2 | ((uint32_t)p3 << 16);
            ((uint2*)(g_zb + (size_t)row * DDIM))[lane] = packed;
            if (lane == 0) g_rowsum[row] = 0.0f;
        }
    }

    // ---------------- grid barrier 1 ----------------------------------------------
    if (tid == 0) {
        __threadfence();
        atomicAdd(&g_cnt1, 1u);
        while (*(volatile unsigned*)&g_cnt1 < NCTA) { }
        __threadfence();
    }
    __syncthreads();

    // ---------------- phase 2: symmetric FP8 GEMM (128x64 tiles) -------------------
    uint32_t d32 = smem_u32(dyn);
    char* base = dyn + ((1024u - (d32 & 1023u)) & 1023u);
    const uint32_t uA  = smem_u32(base);
    const uint32_t uB0 = uA + A_BYTES;
    const uint32_t uB1 = uB0 + B_BYTES;
    float* red_row = (float*)(base + A_BYTES + 2 * B_BYTES);   // [2][128]
    float* red_col = red_row + 2 * BM;                         // [4][64]

    // hoisted ldsm addresses: addr = P + ((ks<<5) ^ S)
    const int hl = lane >> 4;
    uint32_t PA[2], SA[2];
    #pragma unroll
    for (int mf = 0; mf < 2; mf++) {
        int r = wm * 32 + mf * 16 + (lane & 15);
        PA[mf] = uA + (uint32_t)r * 256u + (uint32_t)((hl ^ (r & 1)) << 4);
        SA[mf] = (uint32_t)((r & 6) << 4);
    }
    uint32_t PBo[2], SB[2];
    #pragma unroll
    for (int ng = 0; ng < 2; ng++) {
        int rn = wn * 32 + ng * 16 + (lane & 15);
        PBo[ng] = (uint32_t)rn * 256u + (uint32_t)((hl ^ (rn & 1)) << 4);
        SB[ng] = (uint32_t)((rn & 6) << 4);
    }

    // balanced chunk over 4160 tiles: 16 CTAs get 15, rest 14 (296*14+16 = 4160)
    const int count = 14 + (cta < 16 ? 1 : 0);
    int rem = cta * 14 + (cta < 16 ? cta : 16);
    int p = 0;
    for (;;) {
        int L = 2 * (NTILE - rowof(p));     // cols per row = 128 - 2*ti
        if (rem < L) break;
        rem -= L;
        p++;
    }
    int off = rem;

    int ti = rowof(p);
    load_A(uA, ti * BM, tid);
    load_B(uB0, (2 * ti + off) * BN, tid);
    CP_COMMIT();
    int cur_ti = ti;

    for (int k = 0; k < count; k++) {
        ti = rowof(p);
        const int cj = 2 * ti + off;
        if (ti != cur_ti) {
            load_A(uA, ti * BM, tid);
            CP_COMMIT();
            cur_ti = ti;
        }
        CP_WAIT0();
        __syncthreads();

        if (k + 1 < count) {
            int p2 = p, o2 = off + 1;
            if (o2 >= 2 * (NTILE - rowof(p2))) { o2 = 0; p2++; }
            load_B((k & 1) ? uB0 : uB1, (2 * rowof(p2) + o2) * BN, tid);
            CP_COMMIT();
        }

        const uint32_t uBc = (k & 1) ? uB1 : uB0;
        const int i0 = ti * BM, j0 = cj * BN;
        const bool colsum = (off >= 2);                       // cj >= 2ti+2
        const bool pairt = (ti < 32) && (off >= 64) && (off <= 65);

        float acc[2][4][4];
        #pragma unroll
        for (int mf = 0; mf < 2; mf++)
            #pragma unroll
            for (int nf = 0; nf < 4; nf++)
                #pragma unroll
                for (int c = 0; c < 4; c++) acc[mf][nf][c] = 0.0f;

        // ---- k-loop (8 steps of K=32), register double-buffered fragments ----
        uint32_t af[2][2][4], bf[2][4][2];
        {
            #pragma unroll
            for (int mf = 0; mf < 2; mf++)
                ldsm_x4(PA[mf] + (0u ^ SA[mf]), af[0][mf]);
            #pragma unroll
            for (int ng = 0; ng < 2; ng++) {
                uint32_t q[4];
                ldsm_x4(uBc + PBo[ng] + (0u ^ SB[ng]), q);
                bf[0][ng * 2 + 0][0] = q[0]; bf[0][ng * 2 + 0][1] = q[2];
                bf[0][ng * 2 + 1][0] = q[1]; bf[0][ng * 2 + 1][1] = q[3];
            }
        }
        #pragma unroll
        for (int ks = 0; ks < 8; ks++) {
            const int cur = ks & 1, nxt = cur ^ 1;
            if (ks < 7) {
                const uint32_t kbit = (uint32_t)((ks + 1) << 5);
                #pragma unroll
                for (int mf = 0; mf < 2; mf++)
                    ldsm_x4(PA[mf] + (kbit ^ SA[mf]), af[nxt][mf]);
                #pragma unroll
                for (int ng = 0; ng < 2; ng++) {
                    uint32_t q[4];
                    ldsm_x4(uBc + PBo[ng] + (kbit ^ SB[ng]), q);
                    bf[nxt][ng * 2 + 0][0] = q[0]; bf[nxt][ng * 2 + 0][1] = q[2];
                    bf[nxt][ng * 2 + 1][0] = q[1]; bf[nxt][ng * 2 + 1][1] = q[3];
                }
            }
            #pragma unroll
            for (int mf = 0; mf < 2; mf++)
                #pragma unroll
                for (int nf = 0; nf < 4; nf++)
                    mma_fp8(acc[mf][nf], af[cur][mf], bf[cur][nf]);
        }

        // ---- epilogue: pair capture, exp, diagonal mask, row+col sums ----
        const int rloc = wm * 32 + (lane >> 2);
        const int cloc = wn * 32 + (lane & 3) * 2;
        float cs[8];
        #pragma unroll
        for (int x = 0; x < 8; x++) cs[x] = 0.0f;

        #pragma unroll
        for (int mf = 0; mf < 2; mf++) {
            const int rlo = i0 + rloc + mf * 16;
            const int rhi = rlo + 8;
            float slo = 0.0f, shi = 0.0f;
            #pragma unroll
            for (int nf = 0; nf < 4; nf++) {
                const int col = j0 + cloc + nf * 8;
                if (pairt) {
                    if ((rlo ^ NHALF) == col) {
                        float v = 2.0f * acc[mf][nf][0];
                        g_pair[rlo] = v; g_pair[col] = v;
                    }
                    if ((rlo ^ NHALF) == col + 1) {
                        float v = 2.0f * acc[mf][nf][1];
                        g_pair[rlo] = v; g_pair[col + 1] = v;
                    }
                    if ((rhi ^ NHALF) == col) {
                        float v = 2.0f * acc[mf][nf][2];
                        g_pair[rhi] = v; g_pair[col] = v;
                    }
                    if ((rhi ^ NHALF) == col + 1) {
                        float v = 2.0f * acc[mf][nf][3];
                        g_pair[rhi] = v; g_pair[col + 1] = v;
                    }
                }
                float e0 = __expf(2.0f * acc[mf][nf][0]);
                float e1 = __expf(2.0f * acc[mf][nf][1]);
                float e2 = __expf(2.0f * acc[mf][nf][2]);
                float e3 = __expf(2.0f * acc[mf][nf][3]);
                e0 = (rlo == col)     ? 0.0f : e0;
                e1 = (rlo == col + 1) ? 0.0f : e1;
                e2 = (rhi == col)     ? 0.0f : e2;
                e3 = (rhi == col + 1) ? 0.0f : e3;
                slo += e0 + e1;
                shi += e2 + e3;
                cs[nf * 2]     += e0 + e2;
                cs[nf * 2 + 1] += e1 + e3;
            }
            slo += __shfl_xor_sync(0xFFFFFFFFu, slo, 1);
            slo += __shfl_xor_sync(0xFFFFFFFFu, slo, 2);
            shi += __shfl_xor_sync(0xFFFFFFFFu, shi, 1);
            shi += __shfl_xor_sync(0xFFFFFFFFu, shi, 2);
            if ((lane & 3) == 0) {
                const int lrow = wm * 32 + mf * 16 + (lane >> 2);
                red_row[wn * BM + lrow] = slo;
                red_row[wn * BM + lrow + 8] = shi;
            }
        }
        if (colsum) {
            #pragma unroll
            for (int x = 0; x < 8; x++) {
                cs[x] += __shfl_xor_sync(0xFFFFFFFFu, cs[x], 4);
                cs[x] += __shfl_xor_sync(0xFFFFFFFFu, cs[x], 8);
                cs[x] += __shfl_xor_sync(0xFFFFFFFFu, cs[x], 16);
            }
            if (lane < 4) {
                #pragma unroll
                for (int nf = 0; nf < 4; nf++) {
                    const int c = wn * 32 + nf * 8 + lane * 2;     // 0..63
                    red_col[wm * BN + c]     = cs[nf * 2];
                    red_col[wm * BN + c + 1] = cs[nf * 2 + 1];
                }
            }
        }
        __syncthreads();
        if (tid < BM) {
            float s = red_row[tid] + red_row[BM + tid];
            atomicAdd(&g_rowsum[i0 + tid], s);
        } else if (tid < BM + BN && colsum) {
            const int c = tid - BM;
            float s = red_col[c] + red_col[BN + c]
                    + red_col[2 * BN + c] + red_col[3 * BN + c];
            atomicAdd(&g_rowsum[j0 + c], s);
        }

        off++;
        if (off >= 2 * (NTILE - ti)) { off = 0; p++; }
    }

    // ---------------- grid barrier 2 + CTA0 finish ---------------------------------
    if (tid == 0) {
        __threadfence();
        atomicAdd(&g_cnt2, 1u);
    }
    if (cta == 0) {
        if (tid == 0) {
            while (*(volatile unsigned*)&g_cnt2 < NCTA) { }
            __threadfence();
        }
        __syncthreads();
        __shared__ float sh[NTHREADS];
        float s = 0.0f;
        #pragma unroll
        for (int u = 0; u < NROWS / NTHREADS; u++) {
            const int r = tid + u * NTHREADS;
            s += logf(g_rowsum[r]) - g_pair[r];
        }
        sh[tid] = s;
        __syncthreads();
        for (int o2 = NTHREADS / 2; o2; o2 >>= 1) {
            if (tid < o2) sh[tid] += sh[tid + o2];
            __syncthreads();
        }
        if (tid == 0) {
            out[0] = sh[0] * (1.0f / (float)NROWS);
            g_cnt1 = 0;
            g_cnt2 = 0;
        }
    }
}

// ---------------------------------------------------------------- launch
extern "C" void kernel_launch(void* const* d_in, const int* in_sizes, int n_in,
                              void* d_out, int out_size) {
    const float* z1 = (const float*)d_in[0];
    const float* z2 = (const float*)d_in[1];
    float* out = (float*)d_out;

    static int smem_set = 0;
    if (!smem_set) {
        cudaFuncSetAttribute(k_fused, cudaFuncAttributeMaxDynamicSharedMemorySize,
                             DYN_BYTES);
        smem_set = 1;
    }

    k_fused<<<NCTA, NTHREADS, DYN_BYTES>>>(z1, z2, out);
}